// round 3
// baseline (speedup 1.0000x reference)
#include <cuda_runtime.h>
#include <math.h>

#define NQ   1001   // Q+1 table rows (questions are in [0,1000))
#define KK   5
#define MM   50
#define DK   64
#define DV   128
#define DS   50
#define BB   128
#define SS   2048

#define NBT      (BB*SS)            // 262144
#define OFF_ALPHA  (NBT)            // theta at 0
#define OFF_BETA   (2*NBT)
#define OFF_LOGITS (2*NBT + NBT*4)
#define OFF_PROBS  (2*NBT + NBT*4 + NBT*5)

// ---------------- static scratch (no allocations allowed) ----------------
__device__ float g_W1e[69*DV];          // value_proj_w @ erase_w  (69 x 128)
__device__ float g_b1e[DV];
__device__ float g_W1a[69*DV];          // value_proj_w @ add_w
__device__ float g_b1a[DV];
__device__ float g_attn_tab[NQ*MM];     // softmax(q_e @ key_mem^T) per question
__device__ float g_sumq_tab[NQ*DS];     // q_e @ summary_w[128:192,:] per question
__device__ float g_alpha_tab[NQ];
__device__ float g_beta_tab[NQ*4];
__device__ float g_erase_tab[NQ*KK*DV]; // sigmoid(...) per (q,r)
__device__ float g_add_tab[NQ*KK*DV];   // tanh(...)   per (q,r)
__device__ float g_read[NBT*DV];        // 134 MB scan output

// ---------------- K0: fuse value_proj through erase/add weights ----------
__global__ void fuse_kernel(const float* __restrict__ vp_w, const float* __restrict__ vp_b,
                            const float* __restrict__ er_w, const float* __restrict__ er_b,
                            const float* __restrict__ ad_w, const float* __restrict__ ad_b)
{
    int j = threadIdx.x;                 // 0..127 output column
    int row = blockIdx.x;                // 0..68 weight rows, 69 = bias
    if (row < 69) {
        float ae = 0.f, aa = 0.f;
        #pragma unroll 8
        for (int k = 0; k < DV; k++) {
            float w = vp_w[row*DV + k];
            ae = fmaf(w, er_w[k*DV + j], ae);
            aa = fmaf(w, ad_w[k*DV + j], aa);
        }
        g_W1e[row*DV + j] = ae;
        g_W1a[row*DV + j] = aa;
    } else {
        float be = er_b[j], ba = ad_b[j];
        #pragma unroll 8
        for (int k = 0; k < DV; k++) {
            float b = vp_b[k];
            be = fmaf(b, er_w[k*DV + j], be);
            ba = fmaf(b, ad_w[k*DV + j], ba);
        }
        g_b1e[j] = be;
        g_b1a[j] = ba;
    }
}

// ---------------- K1: per-question tables (attn softmax, sumq, alpha, beta)
__global__ void qtab_kernel(const float* __restrict__ q_embed_w,
                            const float* __restrict__ key_mem,
                            const float* __restrict__ summary_w,
                            const float* __restrict__ alpha_w, const float* __restrict__ alpha_b,
                            const float* __restrict__ beta_w,  const float* __restrict__ beta_b)
{
    int q = blockIdx.x;
    int tid = threadIdx.x;               // 64 threads
    __shared__ float qe[DK];
    __shared__ float lg[MM];
    __shared__ float ex[MM];
    qe[tid] = q_embed_w[q*DK + tid];
    __syncthreads();

    if (tid < MM) {
        float acc = 0.f;
        #pragma unroll 8
        for (int i = 0; i < DK; i++) acc = fmaf(qe[i], key_mem[tid*DK + i], acc);
        lg[tid] = acc;
    }
    __syncthreads();
    if (tid == 0) {
        float mx = lg[0];
        for (int m = 1; m < MM; m++) mx = fmaxf(mx, lg[m]);
        float s = 0.f;
        for (int m = 0; m < MM; m++) { float e = expf(lg[m] - mx); ex[m] = e; s += e; }
        float inv = 1.f / s;
        for (int m = 0; m < MM; m++) g_attn_tab[q*MM + m] = ex[m] * inv;
    }

    if (tid < DS) {
        float acc = 0.f;
        #pragma unroll 8
        for (int i = 0; i < DK; i++)
            acc = fmaf(qe[i], summary_w[(DV + i)*DS + tid], acc);
        g_sumq_tab[q*DS + tid] = acc;
    }
    if (tid == 0) {
        float d = alpha_b[0];
        for (int i = 0; i < DK; i++) d = fmaf(qe[i], alpha_w[i], d);
        g_alpha_tab[q] = (d > 20.f) ? d : log1pf(expf(d));
    }
    if (tid < 4) {
        float d = beta_b[tid];
        for (int i = 0; i < DK; i++) d = fmaf(qe[i], beta_w[i*4 + tid], d);
        g_beta_tab[q*4 + tid] = d;
    }
}

// ---------------- K2: per-(question,response) erase/add tables -----------
__global__ void ertab_kernel(const float* __restrict__ item_embed_w)
{
    int q = blockIdx.x / KK;
    int r = blockIdx.x % KK;
    int j = threadIdx.x;                 // 128 threads
    __shared__ float it[DK];
    if (j < DK) it[j] = item_embed_w[q*DK + j];
    __syncthreads();

    float rf[KK];
    #pragma unroll
    for (int k = 0; k < KK; k++) {
        float d = fabsf((float)k - (float)r) * 0.25f;
        rf[k] = fmaxf(1.f - d, 0.f);
    }
    float pe = g_b1e[j], pa = g_b1a[j];
    #pragma unroll 8
    for (int i = 0; i < DK; i++) {
        float x = it[i];
        pe = fmaf(x, g_W1e[i*DV + j], pe);
        pa = fmaf(x, g_W1a[i*DV + j], pa);
    }
    #pragma unroll
    for (int k = 0; k < KK; k++) {
        pe = fmaf(rf[k], g_W1e[(DK + k)*DV + j], pe);
        pa = fmaf(rf[k], g_W1a[(DK + k)*DV + j], pa);
    }
    int base = (q*KK + r)*DV + j;
    g_erase_tab[base] = 1.f / (1.f + expf(-pe));
    g_add_tab[base]   = tanhf(pa);
}

// ---------------- K3: sequential scan, one block per batch element --------
// Thread v owns memory column mem[0..49][v] entirely in registers.
__global__ void __launch_bounds__(DV, 1)
scan_kernel(const int* __restrict__ questions, const int* __restrict__ responses,
            const float* __restrict__ init_mem)
{
    int b = blockIdx.x;
    int v = threadIdx.x;                 // 0..127
    __shared__ float s_attn[2][MM];

    float mem[MM];
    #pragma unroll
    for (int m = 0; m < MM; m++) mem[m] = init_mem[m*DV + v];

    const int base = b*SS;

    // prologue: stage t=0
    int q0 = questions[base];
    int r0 = responses[base];
    if (v < MM) s_attn[0][v] = g_attn_tab[q0*MM + v];
    float e0 = g_erase_tab[(q0*KK + r0)*DV + v];
    float a0 = g_add_tab  [(q0*KK + r0)*DV + v];

    for (int t = 0; t < SS; t++) {
        // issue global prefetch for t+1 (no shared writes yet)
        float e1 = 0.f, a1 = 0.f, attn_pref = 0.f;
        if (t + 1 < SS) {
            int q1 = questions[base + t + 1];
            int r1 = responses[base + t + 1];
            if (v < MM) attn_pref = g_attn_tab[q1*MM + v];
            e1 = g_erase_tab[(q1*KK + r1)*DV + v];
            a1 = g_add_tab  [(q1*KK + r1)*DV + v];
        }
        __syncthreads();   // s_attn[t&1] ready (written at end of prev iter / prologue)

        const float* at = s_attn[t & 1];
        float rd0 = 0.f, rd1 = 0.f;
        #pragma unroll
        for (int m = 0; m < MM; m += 2) {
            float t0 = at[m];
            rd0 = fmaf(t0, mem[m], rd0);
            float u0  = t0 * e0;
            float tp0 = fmaf(t0, a0, mem[m]);
            mem[m] = fmaf(-u0, mem[m], tp0);

            float t1 = at[m+1];
            rd1 = fmaf(t1, mem[m+1], rd1);
            float u1  = t1 * e0;
            float tp1 = fmaf(t1, a0, mem[m+1]);
            mem[m+1] = fmaf(-u1, mem[m+1], tp1);
        }
        g_read[(base + t)*DV + v] = rd0 + rd1;

        // shared write AFTER all reads of the other buffer this iter;
        // next iter's __syncthreads orders it before its reads.
        if (v < MM && t + 1 < SS) s_attn[(t + 1) & 1][v] = attn_pref;
        e0 = e1; a0 = a1;
    }
}

// ---------------- K4: parallel epilogue — summary/theta/logits/probs ------
__global__ void out_kernel(const int* __restrict__ questions,
                           const float* __restrict__ summary_w,
                           const float* __restrict__ summary_b,
                           const float* __restrict__ theta_w,
                           const float* __restrict__ theta_b,
                           float* __restrict__ out)
{
    int bt = blockIdx.x;
    int tid = threadIdx.x;               // 64 threads
    __shared__ float s_read[DV];
    __shared__ float s_sum[DS];
    int q = questions[bt];
    s_read[tid]      = g_read[bt*DV + tid];
    s_read[tid + 64] = g_read[bt*DV + tid + 64];
    __syncthreads();

    if (tid < DS) {
        float acc = g_sumq_tab[q*DS + tid] + summary_b[tid];
        #pragma unroll 8
        for (int i = 0; i < DV; i++)
            acc = fmaf(s_read[i], summary_w[i*DS + tid], acc);
        s_sum[tid] = tanhf(acc);
    }
    __syncthreads();

    if (tid == 0) {
        float th = theta_b[0];
        #pragma unroll 10
        for (int s = 0; s < DS; s++) th = fmaf(s_sum[s], theta_w[s], th);
        th = tanhf(th);                          // ABILITY_SCALE = 1
        float al = g_alpha_tab[q];
        float inter = th * al;

        float l[5];
        l[0] = 0.f;
        #pragma unroll
        for (int c = 0; c < 4; c++) l[c+1] = l[c] + (inter - g_beta_tab[q*4 + c]);

        float mx = l[0];
        #pragma unroll
        for (int c = 1; c < 5; c++) mx = fmaxf(mx, l[c]);
        float ex[5], s = 0.f;
        #pragma unroll
        for (int c = 0; c < 5; c++) { ex[c] = expf(l[c] - mx); s += ex[c]; }
        float inv = 1.f / s;

        out[bt]             = th;
        out[OFF_ALPHA + bt] = al;
        #pragma unroll
        for (int c = 0; c < 4; c++) out[OFF_BETA + bt*4 + c] = g_beta_tab[q*4 + c];
        #pragma unroll
        for (int c = 0; c < 5; c++) out[OFF_LOGITS + bt*5 + c] = l[c];
        #pragma unroll
        for (int c = 0; c < 5; c++) out[OFF_PROBS  + bt*5 + c] = ex[c] * inv;
    }
}

// ---------------- launch --------------------------------------------------
extern "C" void kernel_launch(void* const* d_in, const int* in_sizes, int n_in,
                              void* d_out, int out_size)
{
    const int*   questions    = (const int*)  d_in[0];
    const int*   responses    = (const int*)  d_in[1];
    const float* q_embed_w    = (const float*)d_in[2];
    const float* item_embed_w = (const float*)d_in[3];
    const float* value_proj_w = (const float*)d_in[4];
    const float* value_proj_b = (const float*)d_in[5];
    const float* key_mem      = (const float*)d_in[6];
    const float* init_mem     = (const float*)d_in[7];
    const float* erase_w      = (const float*)d_in[8];
    const float* erase_b      = (const float*)d_in[9];
    const float* add_w        = (const float*)d_in[10];
    const float* add_b        = (const float*)d_in[11];
    const float* summary_w    = (const float*)d_in[12];
    const float* summary_b    = (const float*)d_in[13];
    const float* theta_w      = (const float*)d_in[14];
    const float* theta_b      = (const float*)d_in[15];
    const float* alpha_w      = (const float*)d_in[16];
    const float* alpha_b      = (const float*)d_in[17];
    const float* beta_w       = (const float*)d_in[18];
    const float* beta_b       = (const float*)d_in[19];
    float* out = (float*)d_out;

    fuse_kernel <<<70, DV>>>(value_proj_w, value_proj_b, erase_w, erase_b, add_w, add_b);
    qtab_kernel <<<NQ, 64>>>(q_embed_w, key_mem, summary_w, alpha_w, alpha_b, beta_w, beta_b);
    ertab_kernel<<<NQ*KK, DV>>>(item_embed_w);
    scan_kernel <<<BB, DV>>>(questions, responses, init_mem);
    out_kernel  <<<NBT, 64>>>(questions, summary_w, summary_b, theta_w, theta_b, out);
}

// round 4
// speedup vs baseline: 1.0368x; 1.0368x over previous
#include <cuda_runtime.h>
#include <math.h>

#define NQ   1001
#define KK   5
#define MM   50
#define DK   64
#define DV   128
#define DS   50
#define BB   128
#define SS   2048

#define NBT      (BB*SS)
#define OFF_ALPHA  (NBT)
#define OFF_BETA   (2*NBT)
#define OFF_LOGITS (2*NBT + NBT*4)
#define OFF_PROBS  (2*NBT + NBT*4 + NBT*5)

typedef unsigned long long u64;

__device__ __forceinline__ u64 fma2(u64 a, u64 b, u64 c) {
    u64 d;
    asm("fma.rn.f32x2 %0, %1, %2, %3;" : "=l"(d) : "l"(a), "l"(b), "l"(c));
    return d;
}
__device__ __forceinline__ u64 pack2(float x, float y) {
    u64 d;
    asm("mov.b64 %0, {%1, %2};" : "=l"(d) : "r"(__float_as_uint(x)), "r"(__float_as_uint(y)));
    return d;
}
__device__ __forceinline__ float2 unpack2(u64 v) {
    float2 f;
    asm("mov.b64 {%0, %1}, %2;" : "=f"(f.x), "=f"(f.y) : "l"(v));
    return f;
}

// ---------------- static scratch ----------------
__device__ float g_W1e[69*DV];
__device__ float g_b1e[DV];
__device__ float g_W1a[69*DV];
__device__ float g_b1a[DV];
__device__ float g_attn_tab[NQ*MM];
__device__ float g_sumq_tab[NQ*DS];     // q_e @ summary_w[128:192,:] + summary_b
__device__ float g_alpha_tab[NQ];
__device__ float g_beta_tab[NQ*4];
__device__ float g_erase_tab[NQ*KK*DV];
__device__ float g_add_tab[NQ*KK*DV];
__device__ float g_read[(size_t)NBT*DV];

// ---------------- K0: fuse value_proj through erase/add ----------
__global__ void fuse_kernel(const float* __restrict__ vp_w, const float* __restrict__ vp_b,
                            const float* __restrict__ er_w, const float* __restrict__ er_b,
                            const float* __restrict__ ad_w, const float* __restrict__ ad_b)
{
    int j = threadIdx.x;
    int row = blockIdx.x;
    if (row < 69) {
        float ae = 0.f, aa = 0.f;
        #pragma unroll 8
        for (int k = 0; k < DV; k++) {
            float w = vp_w[row*DV + k];
            ae = fmaf(w, er_w[k*DV + j], ae);
            aa = fmaf(w, ad_w[k*DV + j], aa);
        }
        g_W1e[row*DV + j] = ae;
        g_W1a[row*DV + j] = aa;
    } else {
        float be = er_b[j], ba = ad_b[j];
        #pragma unroll 8
        for (int k = 0; k < DV; k++) {
            float b = vp_b[k];
            be = fmaf(b, er_w[k*DV + j], be);
            ba = fmaf(b, ad_w[k*DV + j], ba);
        }
        g_b1e[j] = be;
        g_b1a[j] = ba;
    }
}

// ---------------- K1: per-question tables ----------------
__global__ void qtab_kernel(const float* __restrict__ q_embed_w,
                            const float* __restrict__ key_mem,
                            const float* __restrict__ summary_w,
                            const float* __restrict__ summary_b,
                            const float* __restrict__ alpha_w, const float* __restrict__ alpha_b,
                            const float* __restrict__ beta_w,  const float* __restrict__ beta_b)
{
    int q = blockIdx.x;
    int tid = threadIdx.x;               // 64 threads
    __shared__ float qe[DK];
    __shared__ float lg[MM];
    __shared__ float ex[MM];
    qe[tid] = q_embed_w[q*DK + tid];
    __syncthreads();

    if (tid < MM) {
        float acc = 0.f;
        #pragma unroll 8
        for (int i = 0; i < DK; i++) acc = fmaf(qe[i], key_mem[tid*DK + i], acc);
        lg[tid] = acc;
    }
    __syncthreads();
    if (tid == 0) {
        float mx = lg[0];
        for (int m = 1; m < MM; m++) mx = fmaxf(mx, lg[m]);
        float s = 0.f;
        for (int m = 0; m < MM; m++) { float e = expf(lg[m] - mx); ex[m] = e; s += e; }
        float inv = 1.f / s;
        for (int m = 0; m < MM; m++) g_attn_tab[q*MM + m] = ex[m] * inv;
    }

    if (tid < DS) {
        float acc = summary_b[tid];
        #pragma unroll 8
        for (int i = 0; i < DK; i++)
            acc = fmaf(qe[i], summary_w[(DV + i)*DS + tid], acc);
        g_sumq_tab[q*DS + tid] = acc;
    }
    if (tid == 0) {
        float d = alpha_b[0];
        for (int i = 0; i < DK; i++) d = fmaf(qe[i], alpha_w[i], d);
        g_alpha_tab[q] = (d > 20.f) ? d : log1pf(expf(d));
    }
    if (tid < 4) {
        float d = beta_b[tid];
        for (int i = 0; i < DK; i++) d = fmaf(qe[i], beta_w[i*4 + tid], d);
        g_beta_tab[q*4 + tid] = d;
    }
}

// ---------------- K2: per-(q,r) erase/add tables ----------------
__global__ void ertab_kernel(const float* __restrict__ item_embed_w)
{
    int q = blockIdx.x / KK;
    int r = blockIdx.x % KK;
    int j = threadIdx.x;
    __shared__ float it[DK];
    if (j < DK) it[j] = item_embed_w[q*DK + j];
    __syncthreads();

    float rf[KK];
    #pragma unroll
    for (int k = 0; k < KK; k++) {
        float d = fabsf((float)k - (float)r) * 0.25f;
        rf[k] = fmaxf(1.f - d, 0.f);
    }
    float pe = g_b1e[j], pa = g_b1a[j];
    #pragma unroll 8
    for (int i = 0; i < DK; i++) {
        float x = it[i];
        pe = fmaf(x, g_W1e[i*DV + j], pe);
        pa = fmaf(x, g_W1a[i*DV + j], pa);
    }
    #pragma unroll
    for (int k = 0; k < KK; k++) {
        pe = fmaf(rf[k], g_W1e[(DK + k)*DV + j], pe);
        pa = fmaf(rf[k], g_W1a[(DK + k)*DV + j], pa);
    }
    int base = (q*KK + r)*DV + j;
    g_erase_tab[base] = 1.f / (1.f + expf(-pe));
    g_add_tab[base]   = tanhf(pa);
}

// ---------------- K3: scan — 256 threads, v-pairs packed f32x2, 4-way m-split
// thread = (vp 0..63, mh 0..3); owns m in [mh*13, mh*13+13) (padded to 52)
__global__ void __launch_bounds__(256, 1)
scan_kernel(const int* __restrict__ questions, const int* __restrict__ responses,
            const float* __restrict__ init_mem)
{
    const int tid = threadIdx.x;
    const int vp  = tid & 63;
    const int mh  = tid >> 6;
    const int mbase = mh * 13;
    const u64 SGN = 0x8000000080000000ULL;

    __shared__ u64 s_attn[2][52];     // per-m weight, duplicated in both f32 lanes
    __shared__ u64 s_rd[2][3][64];    // partial reads from mh=1..3

    u64 mem[13];
    #pragma unroll
    for (int j = 0; j < 13; j++) {
        int m = mbase + j;
        if (m < MM) {
            float2 iv = *(const float2*)(init_mem + m*DV + 2*vp);
            mem[j] = pack2(iv.x, iv.y);
        } else {
            mem[j] = 0ULL;
        }
    }

    const int base = blockIdx.x * SS;

    // prologue: stage t = 0
    {
        int q0 = questions[base];
        int r0 = responses[base];
        if (tid < 52) {
            float v = (tid < MM) ? g_attn_tab[q0*MM + tid] : 0.f;
            s_attn[0][tid] = pack2(v, v);
        }
        int eb = (q0*KK + r0)*DV + 2*vp;
        u64 E = *(const u64*)(g_erase_tab + eb);
        u64 A0 = *(const u64*)(g_add_tab + eb);
        // stash in mem of loop vars below via locals
        s_rd[1][0][0] = s_rd[1][0][0];   // no-op, keep structure
        // carried operands:
        // (declared right below)
        (void)E; (void)A0;
    }
    int q0 = questions[base];
    int r0 = responses[base];
    int eb0 = (q0*KK + r0)*DV + 2*vp;
    u64 NE = (*(const u64*)(g_erase_tab + eb0)) ^ SGN;
    u64 A  =  *(const u64*)(g_add_tab   + eb0);

    float2 rd_keep = make_float2(0.f, 0.f);

    for (int t = 0; t < SS; t++) {
        // prefetch t+1 into registers (consumed after this iteration)
        u64 E1 = 0ULL, A1 = 0ULL;
        float at1 = 0.f;
        if (t + 1 < SS) {
            int q1 = questions[base + t + 1];
            int r1 = responses[base + t + 1];
            int eb = (q1*KK + r1)*DV + 2*vp;
            E1 = *(const u64*)(g_erase_tab + eb);
            A1 = *(const u64*)(g_add_tab   + eb);
            if (tid < MM) at1 = g_attn_tab[q1*MM + tid];
        }

        __syncthreads();   // s_attn[t&1] and s_rd[(t-1)&1] ready

        // deferred reduction + store for step t-1 (mh==0 warps only)
        if (mh == 0 && t > 0) {
            int cb = (t - 1) & 1;
            float2 p0 = unpack2(s_rd[cb][0][vp]);
            float2 p1 = unpack2(s_rd[cb][1][vp]);
            float2 p2 = unpack2(s_rd[cb][2][vp]);
            float2 o;
            o.x = rd_keep.x + p0.x + p1.x + p2.x;
            o.y = rd_keep.y + p0.y + p1.y + p2.y;
            *(float2*)(g_read + (size_t)(base + t - 1)*DV + 2*vp) = o;
        }

        // core: 13 m-rows, 3 packed FMAs each
        const u64* at = s_attn[t & 1] + mbase;
        u64 rd = 0ULL;
        #pragma unroll
        for (int j = 0; j < 13; j++) {
            u64 T = at[j];                       // LDS.64, broadcast
            rd = fma2(T, mem[j], rd);            // read (pre-update)
            u64 tmp = fma2(NE, mem[j], A);       // a - e*mem
            mem[j]  = fma2(T, tmp, mem[j]);      // mem + t*(a - e*mem)
        }

        if (mh == 0) rd_keep = unpack2(rd);
        else         s_rd[t & 1][mh - 1][vp] = rd;

        if (tid < 52 && t + 1 < SS)
            s_attn[(t + 1) & 1][tid] = pack2(at1, at1);

        NE = E1 ^ SGN;
        A  = A1;
    }

    __syncthreads();
    if (mh == 0) {
        int cb = (SS - 1) & 1;
        float2 p0 = unpack2(s_rd[cb][0][vp]);
        float2 p1 = unpack2(s_rd[cb][1][vp]);
        float2 p2 = unpack2(s_rd[cb][2][vp]);
        float2 o;
        o.x = rd_keep.x + p0.x + p1.x + p2.x;
        o.y = rd_keep.y + p0.y + p1.y + p2.y;
        *(float2*)(g_read + (size_t)(base + SS - 1)*DV + 2*vp) = o;
    }
}

// ---------------- K4: epilogue — W cached in registers, 32 bt per block ----
#define TB 32
__global__ void __launch_bounds__(128)
out_kernel(const int* __restrict__ questions,
           const float* __restrict__ summary_w,
           const float* __restrict__ theta_w,
           const float* __restrict__ theta_b,
           float* __restrict__ out)
{
    const int tid = threadIdx.x;
    const int s   = tid & 63;
    const int ih  = tid >> 6;              // which half of i-dim (0: i<64, 1: i>=64)

    __shared__ float s_read[DV];
    __shared__ float s_part[64];
    __shared__ float s_sum[52];

    // register-cache this thread's 64 summary_w values (amortized over TB rows)
    const int sc = (s < DS) ? s : 0;
    float w[64];
    #pragma unroll
    for (int j = 0; j < 64; j++)
        w[j] = summary_w[(ih*64 + j)*DS + sc];

    float tw0 = 0.f, tw1 = 0.f;
    if (tid < 25) { tw0 = theta_w[2*tid]; tw1 = theta_w[2*tid + 1]; }
    const float tb0 = theta_b[0];

    const int bt0 = blockIdx.x * TB;
    for (int k = 0; k < TB; k++) {
        const int bt = bt0 + k;
        s_read[tid] = g_read[(size_t)bt*DV + tid];
        const int q = questions[bt];
        __syncthreads();

        float acc = 0.f;
        const float4* r4 = (const float4*)(s_read + ih*64);
        #pragma unroll
        for (int j = 0; j < 16; j++) {
            float4 rv = r4[j];                 // LDS.128 broadcast
            acc = fmaf(rv.x, w[4*j+0], acc);
            acc = fmaf(rv.y, w[4*j+1], acc);
            acc = fmaf(rv.z, w[4*j+2], acc);
            acc = fmaf(rv.w, w[4*j+3], acc);
        }
        if (ih == 1) s_part[s] = acc;
        __syncthreads();

        if (ih == 0 && s < DS) {
            float tot = acc + s_part[s] + g_sumq_tab[q*DS + s];  // bias folded in
            s_sum[s] = tanhf(tot);
        }
        __syncthreads();

        if (tid < 32) {
            float p = 0.f;
            if (tid < 25) p = s_sum[2*tid]*tw0 + s_sum[2*tid + 1]*tw1;
            p += __shfl_xor_sync(0xffffffffu, p, 16);
            p += __shfl_xor_sync(0xffffffffu, p, 8);
            p += __shfl_xor_sync(0xffffffffu, p, 4);
            p += __shfl_xor_sync(0xffffffffu, p, 2);
            p += __shfl_xor_sync(0xffffffffu, p, 1);
            if (tid == 0) {
                float th = tanhf(p + tb0);
                float al = g_alpha_tab[q];
                float inter = th * al;

                float l[5];
                l[0] = 0.f;
                #pragma unroll
                for (int c = 0; c < 4; c++)
                    l[c+1] = l[c] + (inter - g_beta_tab[q*4 + c]);

                float mx = l[0];
                #pragma unroll
                for (int c = 1; c < 5; c++) mx = fmaxf(mx, l[c]);
                float ex[5], sm = 0.f;
                #pragma unroll
                for (int c = 0; c < 5; c++) { ex[c] = __expf(l[c] - mx); sm += ex[c]; }
                float inv = 1.f / sm;

                out[bt]             = th;
                out[OFF_ALPHA + bt] = al;
                #pragma unroll
                for (int c = 0; c < 4; c++) out[OFF_BETA + bt*4 + c] = g_beta_tab[q*4 + c];
                #pragma unroll
                for (int c = 0; c < 5; c++) out[OFF_LOGITS + bt*5 + c] = l[c];
                #pragma unroll
                for (int c = 0; c < 5; c++) out[OFF_PROBS  + bt*5 + c] = ex[c] * inv;
            }
        }
    }
}

// ---------------- launch ----------------
extern "C" void kernel_launch(void* const* d_in, const int* in_sizes, int n_in,
                              void* d_out, int out_size)
{
    const int*   questions    = (const int*)  d_in[0];
    const int*   responses    = (const int*)  d_in[1];
    const float* q_embed_w    = (const float*)d_in[2];
    const float* item_embed_w = (const float*)d_in[3];
    const float* value_proj_w = (const float*)d_in[4];
    const float* value_proj_b = (const float*)d_in[5];
    const float* key_mem      = (const float*)d_in[6];
    const float* init_mem     = (const float*)d_in[7];
    const float* erase_w      = (const float*)d_in[8];
    const float* erase_b      = (const float*)d_in[9];
    const float* add_w        = (const float*)d_in[10];
    const float* add_b        = (const float*)d_in[11];
    const float* summary_w    = (const float*)d_in[12];
    const float* summary_b    = (const float*)d_in[13];
    const float* theta_w      = (const float*)d_in[14];
    const float* theta_b      = (const float*)d_in[15];
    const float* alpha_w      = (const float*)d_in[16];
    const float* alpha_b      = (const float*)d_in[17];
    const float* beta_w       = (const float*)d_in[18];
    const float* beta_b       = (const float*)d_in[19];
    float* out = (float*)d_out;

    fuse_kernel <<<70, DV>>>(value_proj_w, value_proj_b, erase_w, erase_b, add_w, add_b);
    qtab_kernel <<<NQ, 64>>>(q_embed_w, key_mem, summary_w, summary_b,
                             alpha_w, alpha_b, beta_w, beta_b);
    ertab_kernel<<<NQ*KK, DV>>>(item_embed_w);
    scan_kernel <<<BB, 256>>>(questions, responses, init_mem);
    out_kernel  <<<NBT/TB, 128>>>(questions, summary_w, theta_w, theta_b, out);
}